// round 3
// baseline (speedup 1.0000x reference)
#include <cuda_runtime.h>
#include <cuda_bf16.h>

// FM layer: out[b,:] = 0.5 * ((sum v*e)^2 - sum (v*e)^2), batch_ids sorted.
// Inputs:
//   d_in[0] feature_embedding float32 [1e6, 64]
//   d_in[1] feature_vals      float32 [819200]
//   d_in[2] batch_ids         int32   [819200] sorted
//   d_in[3] feat_ids          int32   [819200]
//   d_in[4] batch_size        int32   [1]
// Output float32 [4096, 64]

#define EMBED  64
#define GROUPS 16            // 16 groups of 16 threads; each group owns a full row gather
#define GT     16            // threads per group (float4 lanes: dims [4t..4t+3])
#define BLOCK  256

__device__ int g_starts[4097];

// Sorted batch_ids -> CSR row starts. 4 elements per thread, exactly-once, no atomics.
__global__ void boundary_kernel(const int* __restrict__ bids, int nnz, int batch)
{
    int base = 4 * (blockIdx.x * blockDim.x + threadIdx.x);
    if (base > nnz) return;
    int prev = (base == 0) ? -1 : __ldg(bids + base - 1);
    if (base + 3 < nnz) {                      // fast path: aligned int4
        int4 c = __ldg((const int4*)(bids + base));
        int cs[4] = {c.x, c.y, c.z, c.w};
        #pragma unroll
        for (int k = 0; k < 4; k++) {
            for (int b = prev + 1; b <= cs[k]; b++) g_starts[b] = base + k;
            prev = cs[k];
        }
    } else {
        #pragma unroll
        for (int k = 0; k < 4; k++) {
            int p = base + k;
            if (p > nnz) break;
            int cur = (p == nnz) ? batch : __ldg(bids + p);
            for (int b = prev + 1; b <= cur; b++) g_starts[b] = p;
            prev = cur;
        }
    }
}

__device__ __forceinline__ void fm_acc(float v, float4 e, float4& s, float4& q)
{
    float a;
    a = v * e.x; s.x += a; q.x = fmaf(a, a, q.x);
    a = v * e.y; s.y += a; q.y = fmaf(a, a, q.y);
    a = v * e.z; s.z += a; q.z = fmaf(a, a, q.z);
    a = v * e.w; s.w += a; q.w = fmaf(a, a, q.w);
}

__global__ __launch_bounds__(BLOCK, 5)
void fm_main(const float* __restrict__ emb,
             const float* __restrict__ vals,
             const int*   __restrict__ fids,
             float*       __restrict__ out)
{
    const int b = blockIdx.x;
    const int t = threadIdx.x & (GT - 1);     // float4 lane within group
    const int g = threadIdx.x >> 4;           // group 0..15

    const int lo = g_starts[b];
    const int hi = g_starts[b + 1];

    const float4* __restrict__ emb4 = (const float4*)emb;

    float4 s = make_float4(0.f, 0.f, 0.f, 0.f);
    float4 q = make_float4(0.f, 0.f, 0.f, 0.f);

    int lo4 = (lo + 3) & ~3;
    int hi4 = hi & ~3;
    if (lo4 > hi4) { lo4 = hi; hi4 = hi; }    // tiny segment: all scalar head

    // scalar head [lo, lo4)  (<=7 elems, one per group)
    {
        int idx = lo + g;
        if (idx < lo4) {
            int   f = __ldg(fids + idx);
            float v = __ldg(vals + idx);
            float4 e = __ldg(emb4 + f * 16 + t);
            fm_acc(v, e, s, q);
        }
    }
    // scalar tail [hi4, hi)
    {
        int idx = hi4 + g;
        if (idx < hi) {
            int   f = __ldg(fids + idx);
            float v = __ldg(vals + idx);
            float4 e = __ldg(emb4 + f * 16 + t);
            fm_acc(v, e, s, q);
        }
    }

    // vector region: blocks of 4 consecutive elements, group-strided, with
    // prefetch of the next index/val quad.
    int nb = (hi4 - lo4) >> 2;
    int j = g;
    if (j < nb) {
        int4   f = __ldg((const int4*)  (fids + lo4 + 4 * j));
        float4 v = __ldg((const float4*)(vals + lo4 + 4 * j));
        while (true) {
            int jn = j + GROUPS;
            int4 fn; float4 vn;
            bool more = jn < nb;
            if (more) {
                fn = __ldg((const int4*)  (fids + lo4 + 4 * jn));
                vn = __ldg((const float4*)(vals + lo4 + 4 * jn));
            }
            float4 e0 = __ldg(emb4 + f.x * 16 + t);
            float4 e1 = __ldg(emb4 + f.y * 16 + t);
            float4 e2 = __ldg(emb4 + f.z * 16 + t);
            float4 e3 = __ldg(emb4 + f.w * 16 + t);
            fm_acc(v.x, e0, s, q);
            fm_acc(v.y, e1, s, q);
            fm_acc(v.z, e2, s, q);
            fm_acc(v.w, e3, s, q);
            if (!more) break;
            f = fn; v = vn; j = jn;
        }
    }

    // combine 16 groups through shared memory
    __shared__ float4 sh_s[GROUPS][GT];
    __shared__ float4 sh_q[GROUPS][GT];
    sh_s[g][t] = s;
    sh_q[g][t] = q;
    __syncthreads();

    if (threadIdx.x < GT) {
        float4 S = sh_s[0][t], Q = sh_q[0][t];
        #pragma unroll
        for (int k = 1; k < GROUPS; k++) {
            float4 a = sh_s[k][t], c = sh_q[k][t];
            S.x += a.x; S.y += a.y; S.z += a.z; S.w += a.w;
            Q.x += c.x; Q.y += c.y; Q.z += c.z; Q.w += c.w;
        }
        float4 o;
        o.x = 0.5f * (S.x * S.x - Q.x);
        o.y = 0.5f * (S.y * S.y - Q.y);
        o.z = 0.5f * (S.z * S.z - Q.z);
        o.w = 0.5f * (S.w * S.w - Q.w);
        ((float4*)out)[b * GT + t] = o;
    }
}

extern "C" void kernel_launch(void* const* d_in, const int* in_sizes, int n_in,
                              void* d_out, int out_size)
{
    const float* emb  = (const float*)d_in[0];
    const float* vals = (const float*)d_in[1];
    const int*   bids = (const int*)d_in[2];
    const int*   fids = (const int*)d_in[3];
    float* out = (float*)d_out;

    int nnz   = in_sizes[1];
    int batch = out_size / EMBED;   // 4096

    int bthreads = nnz / 4 + 1;
    boundary_kernel<<<(bthreads + 255) / 256, 256>>>(bids, nnz, batch);
    fm_main<<<batch, BLOCK>>>(emb, vals, fids, out);
}

// round 4
// speedup vs baseline: 1.1016x; 1.1016x over previous
#include <cuda_runtime.h>
#include <cuda_bf16.h>

// FM layer: out[b,:] = 0.5 * ((sum v*e)^2 - sum (v*e)^2), batch_ids sorted.
// Inputs:
//   d_in[0] feature_embedding float32 [1e6, 64]
//   d_in[1] feature_vals      float32 [819200]
//   d_in[2] batch_ids         int32   [819200] sorted
//   d_in[3] feat_ids          int32   [819200]
//   d_in[4] batch_size        int32   [1]
// Output float32 [4096, 64]

#define EMBED  64
#define GROUPS 8             // 8 warps per CTA; each warp = one gather group
#define BLOCK  256
#define CHUNK  512           // fids/vals staged through SMEM per chunk (mult of 32)

__device__ int g_starts[4097];

// Sorted batch_ids -> CSR row starts. 4 elems/thread, exactly-once, no atomics.
__global__ void boundary_kernel(const int* __restrict__ bids, int nnz, int batch)
{
    int base = 4 * (blockIdx.x * blockDim.x + threadIdx.x);
    if (base > nnz) return;
    int prev = (base == 0) ? -1 : __ldg(bids + base - 1);
    if (base + 3 < nnz) {
        int4 c = __ldg((const int4*)(bids + base));
        int cs[4] = {c.x, c.y, c.z, c.w};
        #pragma unroll
        for (int k = 0; k < 4; k++) {
            for (int b = prev + 1; b <= cs[k]; b++) g_starts[b] = base + k;
            prev = cs[k];
        }
    } else {
        #pragma unroll
        for (int k = 0; k < 4; k++) {
            int p = base + k;
            if (p > nnz) break;
            int cur = (p == nnz) ? batch : __ldg(bids + p);
            for (int b = prev + 1; b <= cur; b++) g_starts[b] = p;
            prev = cur;
        }
    }
}

__device__ __forceinline__ void fm_acc2(float v, float2 e,
                                        float& sx, float& sy, float& qx, float& qy)
{
    float ax = v * e.x, ay = v * e.y;
    sx += ax; qx = fmaf(ax, ax, qx);
    sy += ay; qy = fmaf(ay, ay, qy);
}

__global__ __launch_bounds__(BLOCK, 6)
void fm_main(const float* __restrict__ emb,
             const float* __restrict__ vals,
             const int*   __restrict__ fids,
             float*       __restrict__ out)
{
    const int b = blockIdx.x;
    const int t = threadIdx.x & 31;     // float2 lane: dims [2t, 2t+1]
    const int g = threadIdx.x >> 5;     // warp/group 0..7

    const int lo = g_starts[b];
    const int hi = g_starts[b + 1];

    const float2* __restrict__ emb2 = (const float2*)emb;

    __shared__ int   sf[CHUNK];
    __shared__ float sv[CHUNK];

    float sx = 0.f, sy = 0.f, qx = 0.f, qy = 0.f;

    for (int base = lo; base < hi; base += CHUNK) {
        int n = hi - base; if (n > CHUNK) n = CHUNK;
        int n_pad = (n + 31) & ~31;

        // stage indices + vals (coalesced, once per chunk)
        for (int j = threadIdx.x; j < n; j += BLOCK) {
            sf[j] = __ldg(fids + base + j);
            sv[j] = __ldg(vals + base + j);
        }
        // zero-pad so the hot loop needs no predicates (row 0 * 0.0 == 0)
        for (int j = n + threadIdx.x; j < n_pad; j += BLOCK) {
            sf[j] = 0; sv[j] = 0.f;
        }
        __syncthreads();

        int rounds = n_pad >> 5;        // 32 elements (4 per group) per round
        if (rounds > 0) {
            int i = g;
            // prologue: gather quad 0
            int f0 = sf[i], f1 = sf[i + 8], f2 = sf[i + 16], f3 = sf[i + 24];
            float2 e0 = __ldg(emb2 + f0 * 32 + t);
            float2 e1 = __ldg(emb2 + f1 * 32 + t);
            float2 e2 = __ldg(emb2 + f2 * 32 + t);
            float2 e3 = __ldg(emb2 + f3 * 32 + t);

            for (int r = 0; r < rounds; r++) {
                float2 p0, p1, p2, p3;
                int ni = i + 32;
                if (r + 1 < rounds) {   // prefetch next quad while current in flight
                    int h0 = sf[ni], h1 = sf[ni + 8], h2 = sf[ni + 16], h3 = sf[ni + 24];
                    p0 = __ldg(emb2 + h0 * 32 + t);
                    p1 = __ldg(emb2 + h1 * 32 + t);
                    p2 = __ldg(emb2 + h2 * 32 + t);
                    p3 = __ldg(emb2 + h3 * 32 + t);
                }
                float v0 = sv[i], v1 = sv[i + 8], v2 = sv[i + 16], v3 = sv[i + 24];
                fm_acc2(v0, e0, sx, sy, qx, qy);
                fm_acc2(v1, e1, sx, sy, qx, qy);
                fm_acc2(v2, e2, sx, sy, qx, qy);
                fm_acc2(v3, e3, sx, sy, qx, qy);
                e0 = p0; e1 = p1; e2 = p2; e3 = p3;
                i = ni;
            }
        }
        __syncthreads();   // protect sf/sv before next chunk refill
    }

    // combine 8 groups through shared memory
    __shared__ float2 sh_s[GROUPS][32];
    __shared__ float2 sh_q[GROUPS][32];
    sh_s[g][t] = make_float2(sx, sy);
    sh_q[g][t] = make_float2(qx, qy);
    __syncthreads();

    if (g == 0) {
        float Sx = sx, Sy = sy, Qx = qx, Qy = qy;
        #pragma unroll
        for (int k = 1; k < GROUPS; k++) {
            float2 a = sh_s[k][t], c = sh_q[k][t];
            Sx += a.x; Sy += a.y;
            Qx += c.x; Qy += c.y;
        }
        float2 o;
        o.x = 0.5f * (Sx * Sx - Qx);
        o.y = 0.5f * (Sy * Sy - Qy);
        ((float2*)out)[b * 32 + t] = o;
    }
}

extern "C" void kernel_launch(void* const* d_in, const int* in_sizes, int n_in,
                              void* d_out, int out_size)
{
    const float* emb  = (const float*)d_in[0];
    const float* vals = (const float*)d_in[1];
    const int*   bids = (const int*)d_in[2];
    const int*   fids = (const int*)d_in[3];
    float* out = (float*)d_out;

    int nnz   = in_sizes[1];
    int batch = out_size / EMBED;   // 4096

    int bthreads = nnz / 4 + 1;
    boundary_kernel<<<(bthreads + 255) / 256, 256>>>(bids, nnz, batch);
    fm_main<<<batch, BLOCK>>>(emb, vals, fids, out);
}

// round 5
// speedup vs baseline: 1.1042x; 1.0023x over previous
#include <cuda_runtime.h>
#include <cuda_bf16.h>

// FM layer: out[b,:] = 0.5 * ((sum v*e)^2 - sum (v*e)^2), batch_ids sorted.
// Inputs:
//   d_in[0] feature_embedding float32 [1e6, 64]
//   d_in[1] feature_vals      float32 [819200]
//   d_in[2] batch_ids         int32   [819200] sorted
//   d_in[3] feat_ids          int32   [819200]
//   d_in[4] batch_size        int32   [1]
// Output float32 [4096, 64]

#define EMBED  64
#define GROUPS 8             // 8 warps per CTA, each handles a quad-strided slice
#define BLOCK  256

__device__ int g_starts[4097];

// Sorted batch_ids -> CSR row starts. 4 elems/thread, exactly-once, no atomics.
__global__ void boundary_kernel(const int* __restrict__ bids, int nnz, int batch)
{
    int base = 4 * (blockIdx.x * blockDim.x + threadIdx.x);
    if (base > nnz) return;
    int prev = (base == 0) ? -1 : __ldg(bids + base - 1);
    if (base + 3 < nnz) {
        int4 c = __ldg((const int4*)(bids + base));
        int cs[4] = {c.x, c.y, c.z, c.w};
        #pragma unroll
        for (int k = 0; k < 4; k++) {
            for (int b = prev + 1; b <= cs[k]; b++) g_starts[b] = base + k;
            prev = cs[k];
        }
    } else {
        #pragma unroll
        for (int k = 0; k < 4; k++) {
            int p = base + k;
            if (p > nnz) break;
            int cur = (p == nnz) ? batch : __ldg(bids + p);
            for (int b = prev + 1; b <= cur; b++) g_starts[b] = p;
            prev = cur;
        }
    }
}

__device__ __forceinline__ void fm_acc2(float v, float2 e,
                                        float& sx, float& sy, float& qx, float& qy)
{
    float ax = v * e.x, ay = v * e.y;
    sx += ax; qx = fmaf(ax, ax, qx);
    sy += ay; qy = fmaf(ay, ay, qy);
}

__global__ __launch_bounds__(BLOCK, 8)
void fm_main(const float* __restrict__ emb,
             const float* __restrict__ vals,
             const int*   __restrict__ fids,
             float*       __restrict__ out)
{
    const int b = blockIdx.x;
    const int t = threadIdx.x & 31;     // float2 lane: dims [2t, 2t+1]
    const int g = threadIdx.x >> 5;     // warp/group 0..7

    const int lo = g_starts[b];
    const int hi = g_starts[b + 1];

    const float2* __restrict__ emb2 = (const float2*)emb;

    float sx = 0.f, sy = 0.f, qx = 0.f, qy = 0.f;

    int lo4 = (lo + 3) & ~3;
    int hi4 = hi & ~3;

    if (lo4 > hi4) {
        // tiny segment (< 8 elems): one scalar element per group
        int idx = lo + g;
        if (idx < hi) {
            int   f = __ldg(fids + idx);
            float v = __ldg(vals + idx);
            float2 e = __ldg(emb2 + f * 32 + t);
            fm_acc2(v, e, sx, sy, qx, qy);
        }
    } else {
        // scalar head [lo, lo4): <=3 elems, one per group
        {
            int idx = lo + g;
            if (idx < lo4) {
                int   f = __ldg(fids + idx);
                float v = __ldg(vals + idx);
                float2 e = __ldg(emb2 + f * 32 + t);
                fm_acc2(v, e, sx, sy, qx, qy);
            }
        }
        // scalar tail [hi4, hi): <=3 elems
        {
            int idx = hi4 + g;
            if (idx < hi) {
                int   f = __ldg(fids + idx);
                float v = __ldg(vals + idx);
                float2 e = __ldg(emb2 + f * 32 + t);
                fm_acc2(v, e, sx, sy, qx, qy);
            }
        }
        // aligned quad region: 1 int4 + 1 float4 broadcast + 4 float2 gathers
        // per 4 elements, group-strided
        int nb = (hi4 - lo4) >> 2;
        for (int j = g; j < nb; j += GROUPS) {
            const int pos = lo4 + 4 * j;
            int4   f = __ldg((const int4*)  (fids + pos));
            float4 v = __ldg((const float4*)(vals + pos));
            float2 e0 = __ldg(emb2 + f.x * 32 + t);
            float2 e1 = __ldg(emb2 + f.y * 32 + t);
            float2 e2 = __ldg(emb2 + f.z * 32 + t);
            float2 e3 = __ldg(emb2 + f.w * 32 + t);
            fm_acc2(v.x, e0, sx, sy, qx, qy);
            fm_acc2(v.y, e1, sx, sy, qx, qy);
            fm_acc2(v.z, e2, sx, sy, qx, qy);
            fm_acc2(v.w, e3, sx, sy, qx, qy);
        }
    }

    // combine 8 groups through shared memory
    __shared__ float2 sh_s[GROUPS][32];
    __shared__ float2 sh_q[GROUPS][32];
    sh_s[g][t] = make_float2(sx, sy);
    sh_q[g][t] = make_float2(qx, qy);
    __syncthreads();

    if (g == 0) {
        float Sx = sx, Sy = sy, Qx = qx, Qy = qy;
        #pragma unroll
        for (int k = 1; k < GROUPS; k++) {
            float2 a = sh_s[k][t], c = sh_q[k][t];
            Sx += a.x; Sy += a.y;
            Qx += c.x; Qy += c.y;
        }
        float2 o;
        o.x = 0.5f * (Sx * Sx - Qx);
        o.y = 0.5f * (Sy * Sy - Qy);
        ((float2*)out)[b * 32 + t] = o;
    }
}

extern "C" void kernel_launch(void* const* d_in, const int* in_sizes, int n_in,
                              void* d_out, int out_size)
{
    const float* emb  = (const float*)d_in[0];
    const float* vals = (const float*)d_in[1];
    const int*   bids = (const int*)d_in[2];
    const int*   fids = (const int*)d_in[3];
    float* out = (float*)d_out;

    int nnz   = in_sizes[1];
    int batch = out_size / EMBED;   // 4096

    int bthreads = nnz / 4 + 1;
    boundary_kernel<<<(bthreads + 255) / 256, 256>>>(bids, nnz, batch);
    fm_main<<<batch, BLOCK>>>(emb, vals, fids, out);
}